// round 9
// baseline (speedup 1.0000x reference)
#include <cuda_runtime.h>
#include <cstddef>

#define NB     8
#define DIMC   64
#define TLEN   16384
#define INNER  128

typedef unsigned long long u64;

// ---------------- device scratch (no allocations allowed) ----------------
__device__ float g_eq[(size_t)NB * INNER * TLEN];          // exp(q), 64 MiB
__device__ float g_sq  [NB * INNER];                       // sum_t exp(q)
__device__ float g_ksum[NB * INNER];                       // sum_t softmax_d(k)
__device__ float g_xsum[NB * DIMC];                        // sum_t x  (for vsum)
__device__ __align__(16) u64 g_A2[(size_t)NB * INNER * 64]; // A dup-pairs, [b][c][o]
__device__ __align__(16) u64 g_W2[2 * 64 * 128];            // W dup-pairs, [g][kk][c]

__device__ __forceinline__ u64 bcast2(float a) {
    u64 r; asm("mov.b64 %0, {%1, %1};" : "=l"(r) : "f"(a)); return r;
}
__device__ __forceinline__ u64 fma2(u64 a, u64 b, u64 c) {
    u64 d; asm("fma.rn.f32x2 %0, %1, %2, %3;" : "=l"(d) : "l"(a), "l"(b), "l"(c)); return d;
}
__device__ __forceinline__ float2 unp2(u64 v) {
    float lo, hi; asm("mov.b64 {%0, %1}, %2;" : "=f"(lo), "=f"(hi) : "l"(v));
    return make_float2(lo, hi);
}
__device__ __forceinline__ void cpa16(void* s, const void* g) {
    unsigned sa = (unsigned)__cvta_generic_to_shared(s);
    asm volatile("cp.async.cg.shared.global [%0], [%1], 16;\n" :: "r"(sa), "l"(g));
}
__device__ __forceinline__ void cpa_commit() {
    asm volatile("cp.async.commit_group;\n" ::: "memory");
}

// ---------------- K0: zero stats + build duplicated/transposed W ----------------
extern "C" __global__ void k_init(const float* __restrict__ w) {
    int gid = blockIdx.x * 256 + threadIdx.x;          // 0..4095
    if (gid < NB * INNER) { g_sq[gid] = 0.f; g_ksum[gid] = 0.f; }
    if (gid < NB * DIMC)  g_xsum[gid] = 0.f;
    #pragma unroll
    for (int j = 0; j < 4; j++) {
        int idx = gid * 4 + j;                         // 0..16383
        int g = idx >> 13, r = idx & 8191;
        int kk = r >> 7, c = r & 127;
        g_W2[idx] = bcast2(w[g * (INNER * DIMC) + c * DIMC + kk]);
    }
}

// ---------------- K1: Q/K GEMM + exp + stats (+ x time-sum) ----------------
// grid (TLEN/128, 2 groups, NB), block 512; per-thread 4c x 8t
extern "C" __global__ void __launch_bounds__(512, 2)
k_qkv(const float* __restrict__ x) {
    extern __shared__ float sm[];
    u64*   ws2   = (u64*)sm;        // [64][128] dup W, 64 KB
    float* xs    = sm + 16384;      // [64][128] x tile, 32 KB
    float* stats = sm;              // alias over ws2 after mainloop

    const int tid = threadIdx.x;
    const int g  = blockIdx.y;
    const int b  = blockIdx.z;
    const int t0 = blockIdx.x * 128;

    // W tile: coalesced copy of pre-duplicated pairs (L2-resident)
    const ulonglong2* wsrc = (const ulonglong2*)(g_W2 + g * 8192);
    #pragma unroll
    for (int i = 0; i < 4096; i += 512)
        ((ulonglong2*)ws2)[i + tid] = wsrc[i + tid];
    // x tile (naturally [dim][t], coalesced float4)
    const float* xb = x + ((size_t)b * DIMC) * TLEN + t0;
    #pragma unroll
    for (int i = 0; i < 2048; i += 512) {
        int idx = i + tid;
        int kk = idx >> 5, t4 = idx & 31;
        ((float4*)xs)[idx] = *(const float4*)&xb[(size_t)kk * TLEN + t4 * 4];
    }
    __syncthreads();

    const int tx = tid & 15, ty = tid >> 4;   // ty 0..31
    const int cb = ty * 4;     // 4 channels per thread
    const int ta = tx * 4;     // t quads: [ta, ta+3] and [64+ta, 64+ta+3]

    u64 acc[4][4];
    #pragma unroll
    for (int i = 0; i < 4; i++)
        #pragma unroll
        for (int j = 0; j < 4; j++) acc[i][j] = 0ull;

    #pragma unroll 4
    for (int kk = 0; kk < 64; kk++) {
        const float* xr = &xs[kk * 128];
        ulonglong2 a0 = *(const ulonglong2*)&xr[ta];
        ulonglong2 a1 = *(const ulonglong2*)&xr[64 + ta];
        u64 xv[4] = { a0.x, a0.y, a1.x, a1.y };
        const u64* wr = &ws2[kk * 128 + cb];
        ulonglong2 w01 = *(const ulonglong2*)&wr[0];
        ulonglong2 w23 = *(const ulonglong2*)&wr[2];
        u64 wv[4] = { w01.x, w01.y, w23.x, w23.y };
        #pragma unroll
        for (int i = 0; i < 4; i++)
            #pragma unroll
            for (int j = 0; j < 4; j++) acc[i][j] = fma2(wv[i], xv[j], acc[i][j]);
    }
    __syncthreads();   // done with ws2; stats region (aliased) now writable

    // unpack: vv[i][0..3] = t=ta+j, vv[i][4..7] = t=64+ta+j
    float vv[4][8];
    #pragma unroll
    for (int i = 0; i < 4; i++)
        #pragma unroll
        for (int j = 0; j < 4; j++) {
            float2 f = unp2(acc[i][j]);
            vv[i][2 * j] = f.x; vv[i][2 * j + 1] = f.y;
        }

    if (g == 0) {
        // ---- q: exp, store eq, accumulate sum_t exp(q); also sum_t x ----
        float* kpart = stats;  // [128][17]
        #pragma unroll
        for (int i = 0; i < 4; i++) {
            float s = 0.f;
            #pragma unroll
            for (int j = 0; j < 8; j++) { vv[i][j] = __expf(vv[i][j]); s += vv[i][j]; }
            size_t base = ((size_t)(b * INNER + cb + i)) * TLEN + t0;
            *(float4*)&g_eq[base + ta]      = make_float4(vv[i][0], vv[i][1], vv[i][2], vv[i][3]);
            *(float4*)&g_eq[base + 64 + ta] = make_float4(vv[i][4], vv[i][5], vv[i][6], vv[i][7]);
            kpart[(cb + i) * 17 + tx] = s;
        }
        // sum_t x from the (still valid) xs tile: 8 lanes per row, 16 floats each
        {
            int row = tid >> 3, l8 = tid & 7;
            const float* xr = &xs[row * 128 + l8 * 4];
            float s = 0.f;
            #pragma unroll
            for (int q4 = 0; q4 < 4; q4++) {
                float4 v4 = *(const float4*)&xr[q4 * 32];
                s += v4.x + v4.y + v4.z + v4.w;
            }
            s += __shfl_down_sync(0xffffffffu, s, 1, 8);
            s += __shfl_down_sync(0xffffffffu, s, 2, 8);
            s += __shfl_down_sync(0xffffffffu, s, 4, 8);
            if (l8 == 0) atomicAdd(&g_xsum[b * DIMC + row], s);
        }
        __syncthreads();
        if (tid < 128) {
            float s = 0.f;
            #pragma unroll
            for (int xk = 0; xk < 16; xk++) s += kpart[tid * 17 + xk];
            atomicAdd(&g_sq[b * INNER + tid], s);
        }
    } else {
        // ---- k: softmax over head-dim (32 ch per head), then sum over t ----
        float* pden  = stats;          // [32][128]
        float* rden  = stats + 4096;   // [4][128]
        float* kpart = stats + 4608;   // [128][17]
        float pd[8];
        #pragma unroll
        for (int j = 0; j < 8; j++) pd[j] = 0.f;
        #pragma unroll
        for (int i = 0; i < 4; i++)
            #pragma unroll
            for (int j = 0; j < 8; j++) { vv[i][j] = __expf(vv[i][j]); pd[j] += vv[i][j]; }
        *(float4*)&pden[ty * 128 + ta]      = make_float4(pd[0], pd[1], pd[2], pd[3]);
        *(float4*)&pden[ty * 128 + 64 + ta] = make_float4(pd[4], pd[5], pd[6], pd[7]);
        __syncthreads();
        {
            int h = tid >> 7, t = tid & 127;   // 512 = 4 heads x 128 t
            float d = 0.f;
            #pragma unroll
            for (int j = 0; j < 8; j++) d += pden[(8 * h + j) * 128 + t];
            rden[h * 128 + t] = 1.0f / d;
        }
        __syncthreads();
        const int h = ty >> 3;
        float4 r0 = *(const float4*)&rden[h * 128 + ta];
        float4 r1 = *(const float4*)&rden[h * 128 + 64 + ta];
        float rr[8] = { r0.x, r0.y, r0.z, r0.w, r1.x, r1.y, r1.z, r1.w };
        #pragma unroll
        for (int i = 0; i < 4; i++) {
            float s = 0.f;
            #pragma unroll
            for (int j = 0; j < 8; j++) s += vv[i][j] * rr[j];
            kpart[(cb + i) * 17 + tx] = s;
        }
        __syncthreads();
        if (tid < 128) {
            float s = 0.f;
            #pragma unroll
            for (int xk = 0; xk < 16; xk++) s += kpart[tid * 17 + xk];
            atomicAdd(&g_ksum[b * INNER + tid], s);
        }
    }
}

// ---------------- K2: vsum = W_v @ xsum;  A2[b][c][o] = dup(w_out[o][c]*scale[c]) --
extern "C" __global__ void k_prepA(const float* __restrict__ w,
                                   const float* __restrict__ w_out) {
    __shared__ float sc[INNER];
    const int b = blockIdx.x;
    const int tid = threadIdx.x;
    if (tid < INNER) {
        const float* wv = w + 2 * INNER * DIMC + tid * DIMC;  // W_v row
        float s = 0.f;
        #pragma unroll
        for (int k = 0; k < DIMC; k++) s += wv[k] * g_xsum[b * DIMC + k];
        sc[tid] = g_ksum[b * INNER + tid] * s / g_sq[b * INNER + tid];
    }
    __syncthreads();
    for (int idx = tid; idx < INNER * 64; idx += 256) {
        int c = idx >> 6, o = idx & 63;
        g_A2[((size_t)b * INNER + c) * 64 + o] = bcast2(w_out[o * INNER + c] * sc[c]);
    }
}

// ---------------- K3: y = A @ eq + b_out ----------------
// grid (TLEN/256, NB), block 512; tile 64 o x 256 t, per-thread 4o x 8t
// K=128 in 8 chunks of 16, cp.async double-buffered
#define CHUNK 16
extern "C" __global__ void __launch_bounds__(512, 2)
k_out(const float* __restrict__ bo, float* __restrict__ y) {
    extern __shared__ float sm[];
    u64*   As2 = (u64*)sm;        // [128][64] dup A (transposed), 64 KB
    float* es  = sm + 16384;      // [2][16][256] eq chunks, 32 KB

    const int tid = threadIdx.x;
    const int b = blockIdx.y;
    const int t0 = blockIdx.x * 256;

    const ulonglong2* Ag = (const ulonglong2*)(g_A2 + (size_t)b * INNER * 64);
    #pragma unroll
    for (int i = 0; i < 4096; i += 512)
        ((ulonglong2*)As2)[i + tid] = Ag[i + tid];

    const float* ep = g_eq + ((size_t)b * INNER) * TLEN + t0;
    const int lrow = tid >> 6;          // 0..7
    const int lt4  = (tid & 63) * 4;    // 0..252

    // prologue: chunk 0 -> buf 0
    {
        const float* src = ep + (size_t)lrow * TLEN + lt4;
        float* dst = es + lrow * 256 + lt4;
        #pragma unroll
        for (int r = 0; r < CHUNK; r += 8)
            cpa16(dst + r * 256, src + (size_t)r * TLEN);
        cpa_commit();
    }

    const int tx = tid & 31, ty = tid >> 5;   // ty 0..15 (one per warp)
    const int ob = ty * 4;     // 4 out channels
    const int ta = tx * 4;     // t quads: [ta] and [128+ta]

    u64 acc[4][4];
    #pragma unroll
    for (int i = 0; i < 4; i++)
        #pragma unroll
        for (int j = 0; j < 4; j++) acc[i][j] = 0ull;

    for (int cc = 0; cc < 8; cc++) {
        if (cc + 1 < 8) {
            const float* src = ep + ((size_t)((cc + 1) * CHUNK + lrow)) * TLEN + lt4;
            float* dst = es + ((cc + 1) & 1) * 4096 + lrow * 256 + lt4;
            #pragma unroll
            for (int r = 0; r < CHUNK; r += 8)
                cpa16(dst + r * 256, src + (size_t)r * TLEN);
            cpa_commit();
            asm volatile("cp.async.wait_group 1;\n" ::: "memory");
        } else {
            asm volatile("cp.async.wait_group 0;\n" ::: "memory");
        }
        __syncthreads();

        const float* eb = es + (cc & 1) * 4096;
        #pragma unroll 4
        for (int ci = 0; ci < CHUNK; ci++) {
            const u64* ar = &As2[(cc * CHUNK + ci) * 64 + ob];
            ulonglong2 a01 = *(const ulonglong2*)&ar[0];
            ulonglong2 a23 = *(const ulonglong2*)&ar[2];
            u64 av[4] = { a01.x, a01.y, a23.x, a23.y };
            const float* er = &eb[ci * 256];
            ulonglong2 e0 = *(const ulonglong2*)&er[ta];
            ulonglong2 e1 = *(const ulonglong2*)&er[128 + ta];
            u64 xv[4] = { e0.x, e0.y, e1.x, e1.y };
            #pragma unroll
            for (int i = 0; i < 4; i++)
                #pragma unroll
                for (int j = 0; j < 4; j++) acc[i][j] = fma2(av[i], xv[j], acc[i][j]);
        }
        __syncthreads();
    }

    #pragma unroll
    for (int i = 0; i < 4; i++) {
        float bias = __ldg(&bo[ob + i]);
        float2 f0 = unp2(acc[i][0]), f1 = unp2(acc[i][1]);
        float2 f2 = unp2(acc[i][2]), f3 = unp2(acc[i][3]);
        size_t base = ((size_t)(b * 64 + ob + i)) * TLEN + t0;
        *(float4*)&y[base + ta]       = make_float4(f0.x + bias, f0.y + bias, f1.x + bias, f1.y + bias);
        *(float4*)&y[base + 128 + ta] = make_float4(f2.x + bias, f2.y + bias, f3.x + bias, f3.y + bias);
    }
}

// ---------------- launch ----------------
extern "C" void kernel_launch(void* const* d_in, const int* in_sizes, int n_in,
                              void* d_out, int out_size) {
    const float* x     = (const float*)d_in[0];
    const float* w_qkv = (const float*)d_in[1];
    const float* w_out = (const float*)d_in[2];
    const float* b_out = (const float*)d_in[3];
    float* y = (float*)d_out;

    cudaFuncSetAttribute(k_qkv, cudaFuncAttributeMaxDynamicSharedMemorySize, 98304);
    cudaFuncSetAttribute(k_out, cudaFuncAttributeMaxDynamicSharedMemorySize, 98304);

    k_init<<<16, 256>>>(w_qkv);
    k_qkv<<<dim3(TLEN / 128, 2, NB), 512, 98304>>>(x);
    k_prepA<<<NB, 256>>>(w_qkv, w_out);
    k_out<<<dim3(TLEN / 256, NB), 512, 98304>>>(b_out, y);
}

// round 12
// speedup vs baseline: 1.0834x; 1.0834x over previous
#include <cuda_runtime.h>
#include <cstddef>

#define NB     8
#define DIMC   64
#define TLEN   16384
#define INNER  128

typedef unsigned long long u64;

// ---------------- device scratch (no allocations allowed) ----------------
__device__ float g_eq[(size_t)NB * INNER * TLEN];          // exp(q), 64 MiB
__device__ float g_sq  [NB * INNER];                       // sum_t exp(q)
__device__ float g_ksum[NB * INNER];                       // sum_t softmax_d(k)
__device__ float g_xsum[NB * DIMC];                        // sum_t x  (for vsum)
__device__ __align__(16) u64 g_A2[(size_t)NB * INNER * 64]; // A dup-pairs, [b][c][o]
__device__ __align__(16) u64 g_W2[2 * 64 * 128];            // W dup-pairs, [g][kk][c]

__device__ __forceinline__ u64 bcast2(float a) {
    u64 r; asm("mov.b64 %0, {%1, %1};" : "=l"(r) : "f"(a)); return r;
}
__device__ __forceinline__ u64 fma2(u64 a, u64 b, u64 c) {
    u64 d; asm("fma.rn.f32x2 %0, %1, %2, %3;" : "=l"(d) : "l"(a), "l"(b), "l"(c)); return d;
}
__device__ __forceinline__ float2 unp2(u64 v) {
    float lo, hi; asm("mov.b64 {%0, %1}, %2;" : "=f"(lo), "=f"(hi) : "l"(v));
    return make_float2(lo, hi);
}
__device__ __forceinline__ void cpa16(void* s, const void* g) {
    unsigned sa = (unsigned)__cvta_generic_to_shared(s);
    asm volatile("cp.async.cg.shared.global [%0], [%1], 16;\n" :: "r"(sa), "l"(g));
}
__device__ __forceinline__ void cpa_commit() {
    asm volatile("cp.async.commit_group;\n" ::: "memory");
}
// sum across the 16-lane half-warp group (tx = lane & 15)
__device__ __forceinline__ float hsum16(float v) {
    v += __shfl_xor_sync(0xffffffffu, v, 1);
    v += __shfl_xor_sync(0xffffffffu, v, 2);
    v += __shfl_xor_sync(0xffffffffu, v, 4);
    v += __shfl_xor_sync(0xffffffffu, v, 8);
    return v;
}

// ---------------- K0: zero stats + build duplicated/transposed W ----------------
extern "C" __global__ void k_init(const float* __restrict__ w) {
    int gid = blockIdx.x * 256 + threadIdx.x;          // 0..4095
    if (gid < NB * INNER) { g_sq[gid] = 0.f; g_ksum[gid] = 0.f; }
    if (gid < NB * DIMC)  g_xsum[gid] = 0.f;
    #pragma unroll
    for (int j = 0; j < 4; j++) {
        int idx = gid * 4 + j;                         // 0..16383
        int g = idx >> 13, r = idx & 8191;
        int kk = r >> 7, c = r & 127;
        g_W2[idx] = bcast2(w[g * (INNER * DIMC) + c * DIMC + kk]);
    }
}

// ---------------- K1: Q/K GEMM + exp + stats (+ x time-sum) ----------------
// grid (TLEN/128, 2 groups, NB), block 256; per-thread 8c x 8t
extern "C" __global__ void __launch_bounds__(256, 2)
k_qkv(const float* __restrict__ x) {
    extern __shared__ float sm[];
    u64*   ws2   = (u64*)sm;        // [64][128] dup W, 64 KB
    float* xs    = sm + 16384;      // [64][128] x tile, 32 KB
    float* stats = sm;              // alias over ws2 after mainloop (k path only)

    const int tid = threadIdx.x;
    const int g  = blockIdx.y;
    const int b  = blockIdx.z;
    const int t0 = blockIdx.x * 128;

    // W tile + x tile via cp.async (no LDG->STS register round trip)
    {
        const ulonglong2* wsrc = (const ulonglong2*)(g_W2 + g * 8192);
        ulonglong2* wdst = (ulonglong2*)ws2;
        #pragma unroll
        for (int i = 0; i < 4096; i += 256)
            cpa16(&wdst[i + tid], &wsrc[i + tid]);
        const float* xb = x + ((size_t)b * DIMC) * TLEN + t0;
        #pragma unroll
        for (int i = 0; i < 2048; i += 256) {
            int idx = i + tid;
            int kk = idx >> 5, t4 = idx & 31;
            cpa16(&((float4*)xs)[idx], &xb[(size_t)kk * TLEN + t4 * 4]);
        }
        cpa_commit();
        asm volatile("cp.async.wait_group 0;\n" ::: "memory");
    }
    __syncthreads();

    const int tx = tid & 15, ty = tid >> 4;
    const int cb = ty * 8;     // 8 channels per thread
    const int ta = tx * 4;     // t quads: [ta, ta+3] and [64+ta, 64+ta+3]

    u64 acc[8][4];
    #pragma unroll
    for (int i = 0; i < 8; i++)
        #pragma unroll
        for (int j = 0; j < 4; j++) acc[i][j] = 0ull;

    #pragma unroll 4
    for (int kk = 0; kk < 64; kk++) {
        const float* xr = &xs[kk * 128];
        ulonglong2 a0 = *(const ulonglong2*)&xr[ta];
        ulonglong2 a1 = *(const ulonglong2*)&xr[64 + ta];
        u64 xv[4] = { a0.x, a0.y, a1.x, a1.y };
        const u64* wr = &ws2[kk * 128 + cb];
        ulonglong2 w01 = *(const ulonglong2*)&wr[0];
        ulonglong2 w23 = *(const ulonglong2*)&wr[2];
        ulonglong2 w45 = *(const ulonglong2*)&wr[4];
        ulonglong2 w67 = *(const ulonglong2*)&wr[6];
        u64 wv[8] = { w01.x, w01.y, w23.x, w23.y, w45.x, w45.y, w67.x, w67.y };
        #pragma unroll
        for (int i = 0; i < 8; i++)
            #pragma unroll
            for (int j = 0; j < 4; j++) acc[i][j] = fma2(wv[i], xv[j], acc[i][j]);
    }
    __syncthreads();   // done with ws2; stats region (aliased) writable (k path)

    // unpack: vv[i][0..3] = t=ta+j, vv[i][4..7] = t=64+ta+j
    float vv[8][8];
    #pragma unroll
    for (int i = 0; i < 8; i++)
        #pragma unroll
        for (int j = 0; j < 4; j++) {
            float2 f = unp2(acc[i][j]);
            vv[i][2 * j] = f.x; vv[i][2 * j + 1] = f.y;
        }

    if (g == 0) {
        // ---- q: exp, store eq, accumulate sum_t exp(q) via shfl; also sum_t x ----
        #pragma unroll
        for (int i = 0; i < 8; i++) {
            float s = 0.f;
            #pragma unroll
            for (int j = 0; j < 8; j++) { vv[i][j] = __expf(vv[i][j]); s += vv[i][j]; }
            size_t base = ((size_t)(b * INNER + cb + i)) * TLEN + t0;
            *(float4*)&g_eq[base + ta]      = make_float4(vv[i][0], vv[i][1], vv[i][2], vv[i][3]);
            *(float4*)&g_eq[base + 64 + ta] = make_float4(vv[i][4], vv[i][5], vv[i][6], vv[i][7]);
            s = hsum16(s);
            if (tx == i) atomicAdd(&g_sq[b * INNER + cb + i], s);
        }
        // sum_t x from the (still valid) xs tile: thread -> (row, rotated seg)
        {
            int row = tid >> 2, seg = ((tid & 3) + row) & 3;
            const float* xr = &xs[row * 128 + seg * 32];
            float s = 0.f;
            #pragma unroll
            for (int q4 = 0; q4 < 8; q4++) {
                float4 v4 = *(const float4*)&xr[q4 * 4];
                s += v4.x + v4.y + v4.z + v4.w;
            }
            s += __shfl_down_sync(0xffffffffu, s, 1, 4);
            s += __shfl_down_sync(0xffffffffu, s, 2, 4);
            if ((tid & 3) == 0) atomicAdd(&g_xsum[b * DIMC + row], s);
        }
    } else {
        // ---- k: softmax over head-dim (32 ch per head), then sum over t ----
        float* pden  = stats;          // [16][128]
        float* rden  = stats + 2048;   // [4][128]
        float pd[8];
        #pragma unroll
        for (int j = 0; j < 8; j++) pd[j] = 0.f;
        #pragma unroll
        for (int i = 0; i < 8; i++)
            #pragma unroll
            for (int j = 0; j < 8; j++) { vv[i][j] = __expf(vv[i][j]); pd[j] += vv[i][j]; }
        *(float4*)&pden[ty * 128 + ta]      = make_float4(pd[0], pd[1], pd[2], pd[3]);
        *(float4*)&pden[ty * 128 + 64 + ta] = make_float4(pd[4], pd[5], pd[6], pd[7]);
        __syncthreads();
        for (int idx = tid; idx < 512; idx += 256) {
            int h = idx >> 7, t = idx & 127;
            float d = pden[(4 * h + 0) * 128 + t] + pden[(4 * h + 1) * 128 + t]
                    + pden[(4 * h + 2) * 128 + t] + pden[(4 * h + 3) * 128 + t];
            rden[h * 128 + t] = 1.0f / d;
        }
        __syncthreads();
        const int h = ty >> 2;
        float4 r0 = *(const float4*)&rden[h * 128 + ta];
        float4 r1 = *(const float4*)&rden[h * 128 + 64 + ta];
        float rr[8] = { r0.x, r0.y, r0.z, r0.w, r1.x, r1.y, r1.z, r1.w };
        #pragma unroll
        for (int i = 0; i < 8; i++) {
            float s = 0.f;
            #pragma unroll
            for (int j = 0; j < 8; j++) s += vv[i][j] * rr[j];
            s = hsum16(s);
            if (tx == i) atomicAdd(&g_ksum[b * INNER + cb + i], s);
        }
    }
}

// ---------------- K2: vsum = W_v @ xsum;  A2[b][c][o] = dup(w_out[o][c]*scale[c]) --
extern "C" __global__ void k_prepA(const float* __restrict__ w,
                                   const float* __restrict__ w_out) {
    __shared__ float sc[INNER];
    const int b = blockIdx.x;
    const int tid = threadIdx.x;
    if (tid < INNER) {
        const float* wv = w + 2 * INNER * DIMC + tid * DIMC;  // W_v row
        float s = 0.f;
        #pragma unroll
        for (int k = 0; k < DIMC; k++) s += wv[k] * g_xsum[b * DIMC + k];
        sc[tid] = g_ksum[b * INNER + tid] * s / g_sq[b * INNER + tid];
    }
    __syncthreads();
    for (int idx = tid; idx < INNER * 64; idx += 256) {
        int c = idx >> 6, o = idx & 63;
        g_A2[((size_t)b * INNER + c) * 64 + o] = bcast2(w_out[o * INNER + c] * sc[c]);
    }
}

// ---------------- K3: y = A @ eq + b_out ----------------
// grid (TLEN/256, NB), block 256; tile 64 o x 256 t, per-thread 8o x 8t
// K=128 in 8 chunks of 16; 3-stage cp.async pipeline, ONE barrier per chunk
#define CHUNK 16
extern "C" __global__ void __launch_bounds__(256, 2)
k_out(const float* __restrict__ bo, float* __restrict__ y) {
    extern __shared__ float sm[];
    u64*   As2 = (u64*)sm;        // [128][64] dup A (transposed), 64 KB
    float* es  = sm + 16384;      // [3][16][256] eq chunks, 48 KB

    const int tid = threadIdx.x;
    const int b = blockIdx.y;
    const int t0 = blockIdx.x * 256;

    const ulonglong2* Ag = (const ulonglong2*)(g_A2 + (size_t)b * INNER * 64);
    #pragma unroll
    for (int i = 0; i < 4096; i += 256)
        ((ulonglong2*)As2)[i + tid] = Ag[i + tid];

    const float* ep = g_eq + ((size_t)b * INNER) * TLEN + t0;
    const int lrow = tid >> 6;          // 0..3  (4 rows per pass, 4 passes)
    const int lt4  = (tid & 63) * 4;    // 0..252

    // prologue: chunks 0,1 -> bufs 0,1 (one commit group per chunk)
    #pragma unroll
    for (int s = 0; s < 2; s++) {
        const float* src = ep + ((size_t)(s * CHUNK + lrow)) * TLEN + lt4;
        float* dst = es + s * 4096 + lrow * 256 + lt4;
        #pragma unroll
        for (int r = 0; r < CHUNK; r += 4)
            cpa16(dst + r * 256, src + (size_t)r * TLEN);
        cpa_commit();
    }

    const int tx = tid & 31, ty = tid >> 5;
    const int ob = ty * 8;     // 8 out channels
    const int ta = tx * 4;     // t quads: [ta] and [128+ta]

    u64 acc[8][4];
    #pragma unroll
    for (int i = 0; i < 8; i++)
        #pragma unroll
        for (int j = 0; j < 4; j++) acc[i][j] = 0ull;

    #pragma unroll
    for (int cc = 0; cc < 8; cc++) {
        // wait for chunk cc's data (<=1 younger group may stay in flight)
        if (cc < 7) asm volatile("cp.async.wait_group 1;\n" ::: "memory");
        else        asm volatile("cp.async.wait_group 0;\n" ::: "memory");
        __syncthreads();   // single barrier per chunk (3-buffer rotation)

        // prefetch chunk cc+2 into buf (cc+2)%3 — its last readers ran at
        // iter cc-1 and are past the barrier above.
        if (cc + 2 < 8) {
            const float* src = ep + ((size_t)((cc + 2) * CHUNK + lrow)) * TLEN + lt4;
            float* dst = es + ((cc + 2) % 3) * 4096 + lrow * 256 + lt4;
            #pragma unroll
            for (int r = 0; r < CHUNK; r += 4)
                cpa16(dst + r * 256, src + (size_t)r * TLEN);
            cpa_commit();
        }

        const float* eb = es + (cc % 3) * 4096;
        #pragma unroll 4
        for (int ci = 0; ci < CHUNK; ci++) {
            const u64* ar = &As2[(cc * CHUNK + ci) * 64 + ob];
            ulonglong2 a01 = *(const ulonglong2*)&ar[0];
            ulonglong2 a23 = *(const ulonglong2*)&ar[2];
            ulonglong2 a45 = *(const ulonglong2*)&ar[4];
            ulonglong2 a67 = *(const ulonglong2*)&ar[6];
            u64 av[8] = { a01.x, a01.y, a23.x, a23.y, a45.x, a45.y, a67.x, a67.y };
            const float* er = &eb[ci * 256];
            ulonglong2 e0 = *(const ulonglong2*)&er[ta];
            ulonglong2 e1 = *(const ulonglong2*)&er[128 + ta];
            u64 xv[4] = { e0.x, e0.y, e1.x, e1.y };
            #pragma unroll
            for (int i = 0; i < 8; i++)
                #pragma unroll
                for (int j = 0; j < 4; j++) acc[i][j] = fma2(av[i], xv[j], acc[i][j]);
        }
    }

    #pragma unroll
    for (int i = 0; i < 8; i++) {
        float bias = __ldg(&bo[ob + i]);
        float2 f0 = unp2(acc[i][0]), f1 = unp2(acc[i][1]);
        float2 f2 = unp2(acc[i][2]), f3 = unp2(acc[i][3]);
        size_t base = ((size_t)(b * 64 + ob + i)) * TLEN + t0;
        *(float4*)&y[base + ta]       = make_float4(f0.x + bias, f0.y + bias, f1.x + bias, f1.y + bias);
        *(float4*)&y[base + 128 + ta] = make_float4(f2.x + bias, f2.y + bias, f3.x + bias, f3.y + bias);
    }
}

// ---------------- launch ----------------
extern "C" void kernel_launch(void* const* d_in, const int* in_sizes, int n_in,
                              void* d_out, int out_size) {
    const float* x     = (const float*)d_in[0];
    const float* w_qkv = (const float*)d_in[1];
    const float* w_out = (const float*)d_in[2];
    const float* b_out = (const float*)d_in[3];
    float* y = (float*)d_out;

    cudaFuncSetAttribute(k_qkv, cudaFuncAttributeMaxDynamicSharedMemorySize, 98304);
    cudaFuncSetAttribute(k_out, cudaFuncAttributeMaxDynamicSharedMemorySize, 114688);

    k_init<<<16, 256>>>(w_qkv);
    k_qkv<<<dim3(TLEN / 128, 2, NB), 256, 98304>>>(x);
    k_prepA<<<NB, 256>>>(w_qkv, w_out);
    k_out<<<dim3(TLEN / 256, NB), 256, 114688>>>(b_out, y);
}